// round 15
// baseline (speedup 1.0000x reference)
#include <cuda_runtime.h>
#include <math.h>

#define NN     100000
#define NITEM  80000
#define DD     128
#define DX     64
#define NE     800000
#define NB     4096
#define SCANT  256
#define SCANB  391            // = ceil(NN / 256)

// aggr/rep 4-chunk pipeline (128-row blocks, 782 total)
#define CB0 196
#define CB1 196
#define CB2 196
#define CB3 194

// ---------------- device scratch ----------------
__device__ __align__(16) float g_x [(size_t)NN * DD];
__device__ __align__(16) float g_xw[(size_t)NN * DD];
__device__ __align__(16) float g_h [(size_t)NN * DD];
__device__ int g_deg[NN];
__device__ int g_cnt[NN];
__device__ int g_cur[NN];
__device__ int g_off[NN + 1];
__device__ int g_csr_src[NE];
__device__ int g_psum[SCANB];
__device__ int g_pbase[SCANB];

__device__ __forceinline__ float lrelu(float v) { return v > 0.f ? v : 0.01f * v; }

// ---------------- packed f32x2 helpers (Blackwell FFMA2) ----------------
__device__ __forceinline__ unsigned long long dup2(float a) {
    unsigned long long r;
    asm("mov.b64 %0, {%1, %1};" : "=l"(r) : "r"(__float_as_uint(a)));
    return r;
}
__device__ __forceinline__ void fma2(unsigned long long& d, unsigned long long a,
                                     unsigned long long b) {
    asm("fma.rn.f32x2 %0, %1, %2, %0;" : "+l"(d) : "l"(a), "l"(b));
}
__device__ __forceinline__ float lo32(unsigned long long v) {
    return __uint_as_float((unsigned)v);
}
__device__ __forceinline__ float hi32(unsigned long long v) {
    return __uint_as_float((unsigned)(v >> 32));
}

// 8x4 per-thread microtile GEMM over K=128. A stride 128, B stride LDB.
template <int LDB>
__device__ __forceinline__ void mmtile4(const float* __restrict__ As,
                                        const float* __restrict__ Bs,
                                        int r0, int c0, float (&out)[8][4]) {
    unsigned long long acc[8][2];
    #pragma unroll
    for (int r = 0; r < 8; r++) { acc[r][0] = 0ull; acc[r][1] = 0ull; }
    #pragma unroll 1
    for (int k = 0; k < 128; k += 4) {
        float4 av[8];
        #pragma unroll
        for (int r = 0; r < 8; r++)
            av[r] = *(const float4*)(As + (r0 + r) * 128 + k);
        #pragma unroll
        for (int kk = 0; kk < 4; kk++) {
            ulonglong2 b01 = *(const ulonglong2*)(Bs + (k + kk) * LDB + c0);
            #pragma unroll
            for (int r = 0; r < 8; r++) {
                float a = (kk == 0) ? av[r].x : (kk == 1) ? av[r].y
                        : (kk == 2) ? av[r].z : av[r].w;
                unsigned long long ad = dup2(a);
                fma2(acc[r][0], ad, b01.x);
                fma2(acc[r][1], ad, b01.y);
            }
        }
    }
    #pragma unroll
    for (int r = 0; r < 8; r++) {
        out[r][0] = lo32(acc[r][0]); out[r][1] = hi32(acc[r][0]);
        out[r][2] = lo32(acc[r][1]); out[r][3] = hi32(acc[r][1]);
    }
}

// ---------------- zero counters ----------------
__global__ void k_zero() {
    int i = blockIdx.x * 256 + threadIdx.x;
    if (i < NN) { g_deg[i] = 0; g_cnt[i] = 0; g_cur[i] = 0; }
}

// ---------------- histogram ----------------
__global__ void k_hist(const int* __restrict__ ei) {
    int e = blockIdx.x * 256 + threadIdx.x;
    if (e < NE) {
        atomicAdd(&g_deg[__ldg(ei + e)], 1);
        atomicAdd(&g_cnt[__ldg(ei + NE + e)], 1);
    }
}

// ---------------- parallel scan pass 1: per-block reduction (256 thr) -------------
__global__ void __launch_bounds__(SCANT) k_scan1() {
    __shared__ int sm[SCANT];
    const int t = threadIdx.x, b = blockIdx.x;
    int i = b * SCANT + t;
    sm[t] = (i < NN) ? g_cnt[i] : 0;
    __syncthreads();
    #pragma unroll
    for (int s = SCANT / 2; s > 0; s >>= 1) {
        if (t < s) sm[t] += sm[t + s];
        __syncthreads();
    }
    if (t == 0) g_psum[b] = sm[0];
}

// ---------------- parallel scan pass 2: scan the 391 block sums (1 block) ---------
__global__ void __launch_bounds__(512) k_scan2() {
    __shared__ int sm[512];
    const int t = threadIdx.x;
    int v = (t < SCANB) ? g_psum[t] : 0;
    sm[t] = v;
    __syncthreads();
    #pragma unroll
    for (int off = 1; off < 512; off <<= 1) {
        int u = (t >= off) ? sm[t - off] : 0;
        __syncthreads();
        sm[t] += u;
        __syncthreads();
    }
    if (t < SCANB) g_pbase[t] = sm[t] - v;
    if (t == SCANB - 1) g_off[NN] = sm[t];
}

// ---------------- parallel scan pass 3: block-local scan + base (256 thr) ---------
__global__ void __launch_bounds__(SCANT) k_scan3() {
    __shared__ int sm[SCANT];
    const int t = threadIdx.x, b = blockIdx.x;
    int i = b * SCANT + t;
    int v = (i < NN) ? g_cnt[i] : 0;
    sm[t] = v;
    __syncthreads();
    #pragma unroll
    for (int off = 1; off < SCANT; off <<= 1) {
        int u = (t >= off) ? sm[t - off] : 0;
        __syncthreads();
        sm[t] += u;
        __syncthreads();
    }
    if (i < NN) g_off[i] = g_pbase[b] + sm[t] - v;
}

// ---------------- CSR build ----------------
__global__ void k_build(const int* __restrict__ ei) {
    int e = blockIdx.x * 256 + threadIdx.x;
    if (e >= NE) return;
    int sj = __ldg(ei + e);
    int di = __ldg(ei + NE + e);
    int pos = g_off[di] + atomicAdd(&g_cur[di], 1);
    g_csr_src[pos] = sj;
}

// ---------------- fused GAT aggregation over node range ----------
__global__ void __launch_bounds__(256) k_aggr(const float* __restrict__ bgat,
                                              int base, int count) {
    int gt = blockIdx.x * 256 + threadIdx.x;
    int wi = gt >> 5, lane = gt & 31;
    if (wi >= count) return;
    int w = base + wi;

    float4 xd = *((const float4*)(g_xw + (size_t)w * DD) + lane);
    int p   = __ldg(&g_off[w]);
    int end = __ldg(&g_off[w + 1]);

    float4 acc = make_float4(0.f, 0.f, 0.f, 0.f);
    float s = 0.f;

    float4 a; float dg;
    if (p < end) {
        int sj = __ldg(&g_csr_src[p]);
        a  = *((const float4*)(g_xw + (size_t)sj * DD) + lane);
        dg = (float)__ldg(&g_deg[sj]);
    }
    while (p < end) {
        float4 a_n; float dg_n;
        if (p + 1 < end) {
            int sj = __ldg(&g_csr_src[p + 1]);
            a_n  = *((const float4*)(g_xw + (size_t)sj * DD) + lane);
            dg_n = (float)__ldg(&g_deg[sj]);
        }
        float d = a.x * xd.x + a.y * xd.y + a.z * xd.z + a.w * xd.w;
        #pragma unroll
        for (int o = 16; o; o >>= 1) d += __shfl_xor_sync(0xffffffffu, d, o);
        float gate = 1.f / (1.f + __expf(-rsqrtf(dg) * d));
        float ev = __expf(d * gate);
        s += ev;
        acc.x += ev * a.x; acc.y += ev * a.y;
        acc.z += ev * a.z; acc.w += ev * a.w;
        a = a_n; dg = dg_n; p++;
    }

    float inv_s = 1.f / (s + 1e-16f);
    float4 bb = __ldg((const float4*)bgat + lane);
    float4 h = make_float4(acc.x * inv_s + bb.x, acc.y * inv_s + bb.y,
                           acc.z * inv_s + bb.z, acc.w * inv_s + bb.w);
    float ss = h.x * h.x + h.y * h.y + h.z * h.z + h.w * h.w;
    #pragma unroll
    for (int o = 16; o; o >>= 1) ss += __shfl_xor_sync(0xffffffffu, ss, o);
    float inv = 1.f / fmaxf(sqrtf(ss), 1e-12f);
    h.x = lrelu(h.x * inv); h.y = lrelu(h.y * inv);
    h.z = lrelu(h.z * inv); h.w = lrelu(h.w * inv);
    *((float4*)(g_h + (size_t)w * DD) + lane) = h;
}

// ---------------- fused: x = l2norm(tanh(feat@W.T+b)); xw = x@W_gat ----------------
__global__ void __launch_bounds__(512, 1) k_gemm_fused(
    const float* __restrict__ feat, const float* __restrict__ ufeat,
    const float* __restrict__ Wm, const float* __restrict__ bm,
    const float* __restrict__ Wu, const float* __restrict__ bu,
    const float* __restrict__ Wg)
{
    extern __shared__ float smx[];
    float* As = smx;            // 128 x 128
    float* Bs = smx + 16384;    // 128 x 128
    const int row0 = blockIdx.x * 128;
    const bool user = row0 >= NITEM;
    const float* A    = user ? (ufeat + (size_t)(row0 - NITEM) * DD)
                             : (feat  + (size_t)row0 * DD);
    const float* W    = user ? Wu : Wm;
    const float* bias = user ? bu : bm;
    int rowlim = NN - row0; if (rowlim > 128) rowlim = 128;
    const int tid = threadIdx.x;

    for (int i = tid; i < 128 * 32; i += 512) {
        int r = i >> 5, c4 = i & 31;
        float4 v = make_float4(0.f, 0.f, 0.f, 0.f);
        if (r < rowlim) v = __ldg((const float4*)A + (size_t)r * 32 + c4);
        *(float4*)&As[r * 128 + c4 * 4] = v;
    }
    for (int i = tid; i < 128 * 32; i += 512) {
        int j = i & 127, c4 = i >> 7;
        float4 v = __ldg((const float4*)W + j * 32 + c4);
        Bs[(c4 * 4 + 0) * 128 + j] = v.x;
        Bs[(c4 * 4 + 1) * 128 + j] = v.y;
        Bs[(c4 * 4 + 2) * 128 + j] = v.z;
        Bs[(c4 * 4 + 3) * 128 + j] = v.w;
    }
    __syncthreads();

    const int r0 = (tid >> 5) * 8, c0 = (tid & 31) * 4;
    float v[8][4];
    mmtile4<128>(As, Bs, r0, c0, v);

    float4 bb = __ldg((const float4*)(bias + c0));
    float bcol[4] = {bb.x, bb.y, bb.z, bb.w};
    #pragma unroll
    for (int r = 0; r < 8; r++) {
        float ss = 0.f;
        #pragma unroll
        for (int c = 0; c < 4; c++) {
            float t = tanhf(v[r][c] + bcol[c]);
            v[r][c] = t; ss += t * t;
        }
        #pragma unroll
        for (int o = 16; o; o >>= 1) ss += __shfl_xor_sync(0xffffffffu, ss, o);
        float inv = 1.f / fmaxf(sqrtf(ss), 1e-12f);
        #pragma unroll
        for (int c = 0; c < 4; c++) v[r][c] *= inv;
        int grow = row0 + r0 + r;
        if (grow < NN)
            *(float4*)&g_x[(size_t)grow * 128 + c0] =
                make_float4(v[r][0], v[r][1], v[r][2], v[r][3]);
    }
    __syncthreads();

    #pragma unroll
    for (int r = 0; r < 8; r++)
        *(float4*)&As[(r0 + r) * 128 + c0] =
            make_float4(v[r][0], v[r][1], v[r][2], v[r][3]);
    for (int i = tid; i < 128 * 32; i += 512) {
        int kk = i >> 5, c4 = i & 31;
        float4 w = __ldg((const float4*)Wg + kk * 32 + c4);
        *(float4*)&Bs[kk * 128 + c4 * 4] = w;
    }
    __syncthreads();

    mmtile4<128>(As, Bs, r0, c0, v);
    #pragma unroll
    for (int r = 0; r < 8; r++) {
        int grow = row0 + r0 + r;
        if (grow < NN)
            *(float4*)&g_xw[(size_t)grow * 128 + c0] =
                make_float4(v[r][0], v[r][1], v[r][2], v[r][3]);
    }
}

// ---------------- rep = lrelu(h@Wg1.T+bg1 + lrelu(x@Wl1.T+bl1) + id_emb) ----------------
__global__ void __launch_bounds__(512, 1) k_rep(
    const float* __restrict__ Wl1, const float* __restrict__ bl1,
    const float* __restrict__ Wg1, const float* __restrict__ bg1,
    const float* __restrict__ id_emb, float* __restrict__ rep, int blk0)
{
    extern __shared__ float smx[];
    float* Xs  = smx;            // 128 x 128
    float* Hs  = smx + 16384;    // 128 x 128
    float* W1s = smx + 32768;    // 128 x 64, later epilogue buf
    float* Wgs = smx + 40960;    // 128 x 64
    const int row0 = (blockIdx.x + blk0) * 128;
    int rowlim = NN - row0; if (rowlim > 128) rowlim = 128;
    const int tid = threadIdx.x;

    for (int i = tid; i < 128 * 32; i += 512) {
        int r = i >> 5, c4 = i & 31;
        float4 vx = make_float4(0.f, 0.f, 0.f, 0.f), vh = vx;
        if (r < rowlim) {
            vx = *((const float4*)(g_x + (size_t)(row0 + r) * 128) + c4);
            vh = *((const float4*)(g_h + (size_t)(row0 + r) * 128) + c4);
        }
        *(float4*)&Xs[r * 128 + c4 * 4] = vx;
        *(float4*)&Hs[r * 128 + c4 * 4] = vh;
    }
    for (int i = tid; i < 64 * 32; i += 512) {
        int j = i & 63, c4 = i >> 6;
        float4 v1 = __ldg((const float4*)Wl1 + j * 32 + c4);
        float4 vg = __ldg((const float4*)Wg1 + j * 32 + c4);
        W1s[(c4 * 4 + 0) * 64 + j] = v1.x; W1s[(c4 * 4 + 1) * 64 + j] = v1.y;
        W1s[(c4 * 4 + 2) * 64 + j] = v1.z; W1s[(c4 * 4 + 3) * 64 + j] = v1.w;
        Wgs[(c4 * 4 + 0) * 64 + j] = vg.x; Wgs[(c4 * 4 + 1) * 64 + j] = vg.y;
        Wgs[(c4 * 4 + 2) * 64 + j] = vg.z; Wgs[(c4 * 4 + 3) * 64 + j] = vg.w;
    }
    __syncthreads();

    const int half = tid >> 8, t = tid & 255;
    const int r0 = (t >> 4) * 8, c0 = (t & 15) * 4;
    const float* Ablk = half ? Hs : Xs;
    const float* Wblk = half ? Wgs : W1s;
    float v[8][4];
    mmtile4<64>(Ablk, Wblk, r0, c0, v);
    __syncthreads();

    float* buf = W1s;
    if (half == 0) {
        float4 b0 = __ldg((const float4*)(bl1 + c0));
        float bc[4] = {b0.x, b0.y, b0.z, b0.w};
        #pragma unroll
        for (int r = 0; r < 8; r++) {
            int grow = row0 + r0 + r;
            float4 e0 = make_float4(0.f, 0.f, 0.f, 0.f);
            if (grow < NN)
                e0 = __ldg((const float4*)(id_emb + (size_t)grow * 64 + c0));
            float em[4] = {e0.x, e0.y, e0.z, e0.w};
            #pragma unroll
            for (int c = 0; c < 4; c++)
                buf[(r0 + r) * 64 + c0 + c] = lrelu(v[r][c] + bc[c]) + em[c];
        }
    }
    __syncthreads();
    if (half == 1) {
        float4 b0 = __ldg((const float4*)(bg1 + c0));
        float bc[4] = {b0.x, b0.y, b0.z, b0.w};
        #pragma unroll
        for (int r = 0; r < 8; r++) {
            int grow = row0 + r0 + r;
            if (grow < NN) {
                float o[4];
                #pragma unroll
                for (int c = 0; c < 4; c++)
                    o[c] = lrelu(v[r][c] + bc[c] + buf[(r0 + r) * 64 + c0 + c]);
                *(float4*)&rep[(size_t)grow * 64 + c0] =
                    make_float4(o[0], o[1], o[2], o[3]);
            }
        }
    }
}

// ---------------- batch head ----------------
__global__ void k_batch(const float* __restrict__ rep,
                        const int* __restrict__ un, const int* __restrict__ pit,
                        const int* __restrict__ nit,
                        const float* __restrict__ Wp1, const float* __restrict__ bp1,
                        const float* __restrict__ Wp2, const float* __restrict__ bp2,
                        float* __restrict__ out_pos, float* __restrict__ out_neg,
                        float* __restrict__ out_pred)
{
    int gt = blockIdx.x * 256 + threadIdx.x;
    int w = gt >> 5, lane = gt & 31;
    if (w >= NB) return;
    int iu = __ldg(un + w), ip = __ldg(pit + w), inn = __ldg(nit + w);
    float u0 = __ldg(rep + (size_t)iu * DX + lane), u1 = __ldg(rep + (size_t)iu * DX + 32 + lane);
    float p0 = __ldg(rep + (size_t)ip * DX + lane), p1 = __ldg(rep + (size_t)ip * DX + 32 + lane);
    float n0 = __ldg(rep + (size_t)inn * DX + lane), n1 = __ldg(rep + (size_t)inn * DX + 32 + lane);
    float ps = u0 * p0 + u1 * p1;
    float ns = u0 * n0 + u1 * n1;
    #pragma unroll
    for (int o = 16; o; o >>= 1) {
        ps += __shfl_xor_sync(0xffffffffu, ps, o);
        ns += __shfl_xor_sync(0xffffffffu, ns, o);
    }
    float h0 = __ldg(bp1 + lane), h1 = __ldg(bp1 + lane + 32);
    #pragma unroll 4
    for (int k = 0; k < 128; k++) {
        float srcv = (k < 32) ? u0 : (k < 64) ? u1 : (k < 96) ? p0 : p1;
        float v = __shfl_sync(0xffffffffu, srcv, k & 31);
        h0 += __ldg(Wp1 + lane * 128 + k) * v;
        h1 += __ldg(Wp1 + (lane + 32) * 128 + k) * v;
    }
    h0 = lrelu(h0); h1 = lrelu(h1);
    float pp = __ldg(Wp2 + lane) * h0 + __ldg(Wp2 + lane + 32) * h1;
    #pragma unroll
    for (int o = 16; o; o >>= 1) pp += __shfl_xor_sync(0xffffffffu, pp, o);
    if (lane == 0) {
        out_pos[w] = ps;
        out_neg[w] = ns;
        out_pred[w] = 1.f / (1.f + __expf(-(pp + __ldg(bp2))));
    }
}

// ---------------- launch ----------------
extern "C" void kernel_launch(void* const* d_in, const int* in_sizes, int n_in,
                              void* d_out, int out_size)
{
    const float* feat   = (const float*)d_in[0];
    const float* ufeat  = (const float*)d_in[1];
    const float* Wm     = (const float*)d_in[2];
    const float* bm     = (const float*)d_in[3];
    const float* Wu     = (const float*)d_in[4];
    const float* bu     = (const float*)d_in[5];
    const float* Wgat   = (const float*)d_in[6];
    const float* bgat   = (const float*)d_in[7];
    const float* Wl1    = (const float*)d_in[8];
    const float* bl1    = (const float*)d_in[9];
    const float* Wg1    = (const float*)d_in[10];
    const float* bg1    = (const float*)d_in[11];
    const float* id_emb = (const float*)d_in[12];
    const float* Wp1    = (const float*)d_in[13];
    const float* bp1    = (const float*)d_in[14];
    const float* Wp2    = (const float*)d_in[15];
    const float* bp2    = (const float*)d_in[16];
    const int*   ei     = (const int*)d_in[17];
    const int*   un     = (const int*)d_in[18];
    const int*   pit    = (const int*)d_in[19];
    const int*   nit    = (const int*)d_in[20];

    float* out      = (float*)d_out;
    float* out_pos  = out;
    float* out_neg  = out + NB;
    float* rep      = out + 2 * NB;
    float* out_pred = out + 2 * NB + (size_t)NN * DX;

    static cudaStream_t s_side = nullptr;
    static cudaEvent_t ev_fork = nullptr, ev_join = nullptr, ev_r3 = nullptr;
    static cudaEvent_t ev_a[4] = {nullptr, nullptr, nullptr, nullptr};
    if (!s_side) {
        cudaStreamCreateWithFlags(&s_side, cudaStreamNonBlocking);
        cudaEventCreateWithFlags(&ev_fork, cudaEventDisableTiming);
        cudaEventCreateWithFlags(&ev_join, cudaEventDisableTiming);
        cudaEventCreateWithFlags(&ev_r3,   cudaEventDisableTiming);
        for (int i = 0; i < 4; i++)
            cudaEventCreateWithFlags(&ev_a[i], cudaEventDisableTiming);
        cudaFuncSetAttribute(k_gemm_fused, cudaFuncAttributeMaxDynamicSharedMemorySize, 131072);
        cudaFuncSetAttribute(k_rep,        cudaFuncAttributeMaxDynamicSharedMemorySize, 196608);
    }

    const int cblk[4]  = {CB0, CB1, CB2, CB3};
    const int cbase[4] = {0, CB0, CB0 + CB1, CB0 + CB1 + CB2};

    // fork: CSR build chain on side stream, GEMM on main stream
    cudaEventRecord(ev_fork, 0);
    cudaStreamWaitEvent(s_side, ev_fork, 0);

    k_zero <<<(NN + 255) / 256, 256, 0, s_side>>>();
    k_hist <<<(NE + 255) / 256, 256, 0, s_side>>>(ei);
    k_scan1<<<SCANB, SCANT, 0, s_side>>>();
    k_scan2<<<1, 512, 0, s_side>>>();
    k_scan3<<<SCANB, SCANT, 0, s_side>>>();
    k_build<<<(NE + 255) / 256, 256, 0, s_side>>>(ei);

    k_gemm_fused<<<782, 512, 131072>>>(feat, ufeat, Wm, bm, Wu, bu, Wgat);

    cudaEventRecord(ev_join, s_side);
    cudaStreamWaitEvent(0, ev_join, 0);

    // 4-chunk pipeline: aggr streams on main; rep trails on side
    for (int i = 0; i < 4; i++) {
        int nbase = cbase[i] * 128;
        int ncnt  = cblk[i] * 128;
        if (nbase + ncnt > NN) ncnt = NN - nbase;
        k_aggr<<<(ncnt * 32 + 255) / 256, 256>>>(bgat, nbase, ncnt);
        cudaEventRecord(ev_a[i], 0);
        cudaStreamWaitEvent(s_side, ev_a[i], 0);
        k_rep<<<cblk[i], 512, 196608, s_side>>>(Wl1, bl1, Wg1, bg1, id_emb, rep, cbase[i]);
    }
    cudaEventRecord(ev_r3, s_side);
    cudaStreamWaitEvent(0, ev_r3, 0);

    k_batch<<<NB / 8, 256>>>(rep, un, pit, nit, Wp1, bp1, Wp2, bp2,
                             out_pos, out_neg, out_pred);
}

// round 16
// speedup vs baseline: 1.0184x; 1.0184x over previous
#include <cuda_runtime.h>
#include <math.h>

#define NN     100000
#define NITEM  80000
#define DD     128
#define DX     64
#define NE     800000
#define NB     4096
#define NSPLIT 50048          // = 391 * 128 (proven split)
#define RBLK0  391
#define RBLK1  391
#define SCANT  256
#define SCANB  391            // = ceil(NN / 256)

// ---------------- device scratch ----------------
__device__ __align__(16) float g_x [(size_t)NN * DD];
__device__ __align__(16) float g_xw[(size_t)NN * DD];
__device__ __align__(16) float g_h [(size_t)NN * DD];
__device__ int g_deg[NN];
__device__ int g_cnt[NN];
__device__ int g_cur[NN];
__device__ int g_off[NN + 1];
__device__ int g_csr_src[NE];
__device__ int g_psum[SCANB];
__device__ int g_pbase[SCANB];

__device__ __forceinline__ float lrelu(float v) { return v > 0.f ? v : 0.01f * v; }

// ---------------- packed f32x2 helpers (Blackwell FFMA2) ----------------
__device__ __forceinline__ unsigned long long dup2(float a) {
    unsigned long long r;
    asm("mov.b64 %0, {%1, %1};" : "=l"(r) : "r"(__float_as_uint(a)));
    return r;
}
__device__ __forceinline__ void fma2(unsigned long long& d, unsigned long long a,
                                     unsigned long long b) {
    asm("fma.rn.f32x2 %0, %1, %2, %0;" : "+l"(d) : "l"(a), "l"(b));
}
__device__ __forceinline__ float lo32(unsigned long long v) {
    return __uint_as_float((unsigned)v);
}
__device__ __forceinline__ float hi32(unsigned long long v) {
    return __uint_as_float((unsigned)(v >> 32));
}

// 8x4 per-thread microtile GEMM over K=128. A stride 128, B stride LDB.
template <int LDB>
__device__ __forceinline__ void mmtile4(const float* __restrict__ As,
                                        const float* __restrict__ Bs,
                                        int r0, int c0, float (&out)[8][4]) {
    unsigned long long acc[8][2];
    #pragma unroll
    for (int r = 0; r < 8; r++) { acc[r][0] = 0ull; acc[r][1] = 0ull; }
    #pragma unroll 1
    for (int k = 0; k < 128; k += 4) {
        float4 av[8];
        #pragma unroll
        for (int r = 0; r < 8; r++)
            av[r] = *(const float4*)(As + (r0 + r) * 128 + k);
        #pragma unroll
        for (int kk = 0; kk < 4; kk++) {
            ulonglong2 b01 = *(const ulonglong2*)(Bs + (k + kk) * LDB + c0);
            #pragma unroll
            for (int r = 0; r < 8; r++) {
                float a = (kk == 0) ? av[r].x : (kk == 1) ? av[r].y
                        : (kk == 2) ? av[r].z : av[r].w;
                unsigned long long ad = dup2(a);
                fma2(acc[r][0], ad, b01.x);
                fma2(acc[r][1], ad, b01.y);
            }
        }
    }
    #pragma unroll
    for (int r = 0; r < 8; r++) {
        out[r][0] = lo32(acc[r][0]); out[r][1] = hi32(acc[r][0]);
        out[r][2] = lo32(acc[r][1]); out[r][3] = hi32(acc[r][1]);
    }
}

// ---------------- zero counters ----------------
__global__ void k_zero() {
    int i = blockIdx.x * 256 + threadIdx.x;
    if (i < NN) { g_deg[i] = 0; g_cnt[i] = 0; g_cur[i] = 0; }
}

// ---------------- histogram ----------------
__global__ void k_hist(const int* __restrict__ ei) {
    int e = blockIdx.x * 256 + threadIdx.x;
    if (e < NE) {
        atomicAdd(&g_deg[__ldg(ei + e)], 1);
        atomicAdd(&g_cnt[__ldg(ei + NE + e)], 1);
    }
}

// ---------------- parallel scan pass 1: per-block reduction (256 thr) -------------
__global__ void __launch_bounds__(SCANT) k_scan1() {
    __shared__ int sm[SCANT];
    const int t = threadIdx.x, b = blockIdx.x;
    int i = b * SCANT + t;
    sm[t] = (i < NN) ? g_cnt[i] : 0;
    __syncthreads();
    #pragma unroll
    for (int s = SCANT / 2; s > 0; s >>= 1) {
        if (t < s) sm[t] += sm[t + s];
        __syncthreads();
    }
    if (t == 0) g_psum[b] = sm[0];
}

// ---------------- parallel scan pass 2: scan the 391 block sums (1 block) ---------
__global__ void __launch_bounds__(512) k_scan2() {
    __shared__ int sm[512];
    const int t = threadIdx.x;
    int v = (t < SCANB) ? g_psum[t] : 0;
    sm[t] = v;
    __syncthreads();
    #pragma unroll
    for (int off = 1; off < 512; off <<= 1) {
        int u = (t >= off) ? sm[t - off] : 0;
        __syncthreads();
        sm[t] += u;
        __syncthreads();
    }
    if (t < SCANB) g_pbase[t] = sm[t] - v;
    if (t == SCANB - 1) g_off[NN] = sm[t];
}

// ---------------- parallel scan pass 3: block-local scan + base (256 thr) ---------
__global__ void __launch_bounds__(SCANT) k_scan3() {
    __shared__ int sm[SCANT];
    const int t = threadIdx.x, b = blockIdx.x;
    int i = b * SCANT + t;
    int v = (i < NN) ? g_cnt[i] : 0;
    sm[t] = v;
    __syncthreads();
    #pragma unroll
    for (int off = 1; off < SCANT; off <<= 1) {
        int u = (t >= off) ? sm[t - off] : 0;
        __syncthreads();
        sm[t] += u;
        __syncthreads();
    }
    if (i < NN) g_off[i] = g_pbase[b] + sm[t] - v;
}

// ---------------- CSR build ----------------
__global__ void k_build(const int* __restrict__ ei) {
    int e = blockIdx.x * 256 + threadIdx.x;
    if (e >= NE) return;
    int sj = __ldg(ei + e);
    int di = __ldg(ei + NE + e);
    int pos = g_off[di] + atomicAdd(&g_cur[di], 1);
    g_csr_src[pos] = sj;
}

// ---------------- fused GAT aggregation over node range (512 thr/block) ----------
__global__ void __launch_bounds__(512) k_aggr(const float* __restrict__ bgat,
                                              int base, int count) {
    int gt = blockIdx.x * 512 + threadIdx.x;
    int wi = gt >> 5, lane = gt & 31;
    if (wi >= count) return;
    int w = base + wi;

    float4 xd = *((const float4*)(g_xw + (size_t)w * DD) + lane);
    int p   = __ldg(&g_off[w]);
    int end = __ldg(&g_off[w + 1]);

    float4 acc = make_float4(0.f, 0.f, 0.f, 0.f);
    float s = 0.f;

    float4 a; float dg;
    if (p < end) {
        int sj = __ldg(&g_csr_src[p]);
        a  = *((const float4*)(g_xw + (size_t)sj * DD) + lane);
        dg = (float)__ldg(&g_deg[sj]);
    }
    while (p < end) {
        float4 a_n; float dg_n;
        if (p + 1 < end) {
            int sj = __ldg(&g_csr_src[p + 1]);
            a_n  = *((const float4*)(g_xw + (size_t)sj * DD) + lane);
            dg_n = (float)__ldg(&g_deg[sj]);
        }
        float d = a.x * xd.x + a.y * xd.y + a.z * xd.z + a.w * xd.w;
        #pragma unroll
        for (int o = 16; o; o >>= 1) d += __shfl_xor_sync(0xffffffffu, d, o);
        float gate = 1.f / (1.f + __expf(-rsqrtf(dg) * d));
        float ev = __expf(d * gate);
        s += ev;
        acc.x += ev * a.x; acc.y += ev * a.y;
        acc.z += ev * a.z; acc.w += ev * a.w;
        a = a_n; dg = dg_n; p++;
    }

    float inv_s = 1.f / (s + 1e-16f);
    float4 bb = __ldg((const float4*)bgat + lane);
    float4 h = make_float4(acc.x * inv_s + bb.x, acc.y * inv_s + bb.y,
                           acc.z * inv_s + bb.z, acc.w * inv_s + bb.w);
    float ss = h.x * h.x + h.y * h.y + h.z * h.z + h.w * h.w;
    #pragma unroll
    for (int o = 16; o; o >>= 1) ss += __shfl_xor_sync(0xffffffffu, ss, o);
    float inv = 1.f / fmaxf(sqrtf(ss), 1e-12f);
    h.x = lrelu(h.x * inv); h.y = lrelu(h.y * inv);
    h.z = lrelu(h.z * inv); h.w = lrelu(h.w * inv);
    *((float4*)(g_h + (size_t)w * DD) + lane) = h;
}

// ---------------- fused: x = l2norm(tanh(feat@W.T+b)); xw = x@W_gat ----------------
__global__ void __launch_bounds__(512, 1) k_gemm_fused(
    const float* __restrict__ feat, const float* __restrict__ ufeat,
    const float* __restrict__ Wm, const float* __restrict__ bm,
    const float* __restrict__ Wu, const float* __restrict__ bu,
    const float* __restrict__ Wg)
{
    extern __shared__ float smx[];
    float* As = smx;            // 128 x 128
    float* Bs = smx + 16384;    // 128 x 128
    const int row0 = blockIdx.x * 128;
    const bool user = row0 >= NITEM;
    const float* A    = user ? (ufeat + (size_t)(row0 - NITEM) * DD)
                             : (feat  + (size_t)row0 * DD);
    const float* W    = user ? Wu : Wm;
    const float* bias = user ? bu : bm;
    int rowlim = NN - row0; if (rowlim > 128) rowlim = 128;
    const int tid = threadIdx.x;

    for (int i = tid; i < 128 * 32; i += 512) {
        int r = i >> 5, c4 = i & 31;
        float4 v = make_float4(0.f, 0.f, 0.f, 0.f);
        if (r < rowlim) v = __ldg((const float4*)A + (size_t)r * 32 + c4);
        *(float4*)&As[r * 128 + c4 * 4] = v;
    }
    for (int i = tid; i < 128 * 32; i += 512) {
        int j = i & 127, c4 = i >> 7;
        float4 v = __ldg((const float4*)W + j * 32 + c4);
        Bs[(c4 * 4 + 0) * 128 + j] = v.x;
        Bs[(c4 * 4 + 1) * 128 + j] = v.y;
        Bs[(c4 * 4 + 2) * 128 + j] = v.z;
        Bs[(c4 * 4 + 3) * 128 + j] = v.w;
    }
    __syncthreads();

    const int r0 = (tid >> 5) * 8, c0 = (tid & 31) * 4;
    float v[8][4];
    mmtile4<128>(As, Bs, r0, c0, v);

    float4 bb = __ldg((const float4*)(bias + c0));
    float bcol[4] = {bb.x, bb.y, bb.z, bb.w};
    #pragma unroll
    for (int r = 0; r < 8; r++) {
        float ss = 0.f;
        #pragma unroll
        for (int c = 0; c < 4; c++) {
            float t = tanhf(v[r][c] + bcol[c]);
            v[r][c] = t; ss += t * t;
        }
        #pragma unroll
        for (int o = 16; o; o >>= 1) ss += __shfl_xor_sync(0xffffffffu, ss, o);
        float inv = 1.f / fmaxf(sqrtf(ss), 1e-12f);
        #pragma unroll
        for (int c = 0; c < 4; c++) v[r][c] *= inv;
        int grow = row0 + r0 + r;
        if (grow < NN)
            *(float4*)&g_x[(size_t)grow * 128 + c0] =
                make_float4(v[r][0], v[r][1], v[r][2], v[r][3]);
    }
    __syncthreads();

    #pragma unroll
    for (int r = 0; r < 8; r++)
        *(float4*)&As[(r0 + r) * 128 + c0] =
            make_float4(v[r][0], v[r][1], v[r][2], v[r][3]);
    for (int i = tid; i < 128 * 32; i += 512) {
        int kk = i >> 5, c4 = i & 31;
        float4 w = __ldg((const float4*)Wg + kk * 32 + c4);
        *(float4*)&Bs[kk * 128 + c4 * 4] = w;
    }
    __syncthreads();

    mmtile4<128>(As, Bs, r0, c0, v);
    #pragma unroll
    for (int r = 0; r < 8; r++) {
        int grow = row0 + r0 + r;
        if (grow < NN)
            *(float4*)&g_xw[(size_t)grow * 128 + c0] =
                make_float4(v[r][0], v[r][1], v[r][2], v[r][3]);
    }
}

// ---------------- rep = lrelu(h@Wg1.T+bg1 + lrelu(x@Wl1.T+bl1) + id_emb) ----------------
__global__ void __launch_bounds__(512, 1) k_rep(
    const float* __restrict__ Wl1, const float* __restrict__ bl1,
    const float* __restrict__ Wg1, const float* __restrict__ bg1,
    const float* __restrict__ id_emb, float* __restrict__ rep, int blk0)
{
    extern __shared__ float smx[];
    float* Xs  = smx;            // 128 x 128
    float* Hs  = smx + 16384;    // 128 x 128
    float* W1s = smx + 32768;    // 128 x 64, later epilogue buf
    float* Wgs = smx + 40960;    // 128 x 64
    const int row0 = (blockIdx.x + blk0) * 128;
    int rowlim = NN - row0; if (rowlim > 128) rowlim = 128;
    const int tid = threadIdx.x;

    for (int i = tid; i < 128 * 32; i += 512) {
        int r = i >> 5, c4 = i & 31;
        float4 vx = make_float4(0.f, 0.f, 0.f, 0.f), vh = vx;
        if (r < rowlim) {
            vx = *((const float4*)(g_x + (size_t)(row0 + r) * 128) + c4);
            vh = *((const float4*)(g_h + (size_t)(row0 + r) * 128) + c4);
        }
        *(float4*)&Xs[r * 128 + c4 * 4] = vx;
        *(float4*)&Hs[r * 128 + c4 * 4] = vh;
    }
    for (int i = tid; i < 64 * 32; i += 512) {
        int j = i & 63, c4 = i >> 6;
        float4 v1 = __ldg((const float4*)Wl1 + j * 32 + c4);
        float4 vg = __ldg((const float4*)Wg1 + j * 32 + c4);
        W1s[(c4 * 4 + 0) * 64 + j] = v1.x; W1s[(c4 * 4 + 1) * 64 + j] = v1.y;
        W1s[(c4 * 4 + 2) * 64 + j] = v1.z; W1s[(c4 * 4 + 3) * 64 + j] = v1.w;
        Wgs[(c4 * 4 + 0) * 64 + j] = vg.x; Wgs[(c4 * 4 + 1) * 64 + j] = vg.y;
        Wgs[(c4 * 4 + 2) * 64 + j] = vg.z; Wgs[(c4 * 4 + 3) * 64 + j] = vg.w;
    }
    __syncthreads();

    const int half = tid >> 8, t = tid & 255;
    const int r0 = (t >> 4) * 8, c0 = (t & 15) * 4;
    const float* Ablk = half ? Hs : Xs;
    const float* Wblk = half ? Wgs : W1s;
    float v[8][4];
    mmtile4<64>(Ablk, Wblk, r0, c0, v);
    __syncthreads();

    float* buf = W1s;
    if (half == 0) {
        float4 b0 = __ldg((const float4*)(bl1 + c0));
        float bc[4] = {b0.x, b0.y, b0.z, b0.w};
        #pragma unroll
        for (int r = 0; r < 8; r++) {
            int grow = row0 + r0 + r;
            float4 e0 = make_float4(0.f, 0.f, 0.f, 0.f);
            if (grow < NN)
                e0 = __ldg((const float4*)(id_emb + (size_t)grow * 64 + c0));
            float em[4] = {e0.x, e0.y, e0.z, e0.w};
            #pragma unroll
            for (int c = 0; c < 4; c++)
                buf[(r0 + r) * 64 + c0 + c] = lrelu(v[r][c] + bc[c]) + em[c];
        }
    }
    __syncthreads();
    if (half == 1) {
        float4 b0 = __ldg((const float4*)(bg1 + c0));
        float bc[4] = {b0.x, b0.y, b0.z, b0.w};
        #pragma unroll
        for (int r = 0; r < 8; r++) {
            int grow = row0 + r0 + r;
            if (grow < NN) {
                float o[4];
                #pragma unroll
                for (int c = 0; c < 4; c++)
                    o[c] = lrelu(v[r][c] + bc[c] + buf[(r0 + r) * 64 + c0 + c]);
                *(float4*)&rep[(size_t)grow * 64 + c0] =
                    make_float4(o[0], o[1], o[2], o[3]);
            }
        }
    }
}

// ---------------- batch head ----------------
__global__ void k_batch(const float* __restrict__ rep,
                        const int* __restrict__ un, const int* __restrict__ pit,
                        const int* __restrict__ nit,
                        const float* __restrict__ Wp1, const float* __restrict__ bp1,
                        const float* __restrict__ Wp2, const float* __restrict__ bp2,
                        float* __restrict__ out_pos, float* __restrict__ out_neg,
                        float* __restrict__ out_pred)
{
    int gt = blockIdx.x * 256 + threadIdx.x;
    int w = gt >> 5, lane = gt & 31;
    if (w >= NB) return;
    int iu = __ldg(un + w), ip = __ldg(pit + w), inn = __ldg(nit + w);
    float u0 = __ldg(rep + (size_t)iu * DX + lane), u1 = __ldg(rep + (size_t)iu * DX + 32 + lane);
    float p0 = __ldg(rep + (size_t)ip * DX + lane), p1 = __ldg(rep + (size_t)ip * DX + 32 + lane);
    float n0 = __ldg(rep + (size_t)inn * DX + lane), n1 = __ldg(rep + (size_t)inn * DX + 32 + lane);
    float ps = u0 * p0 + u1 * p1;
    float ns = u0 * n0 + u1 * n1;
    #pragma unroll
    for (int o = 16; o; o >>= 1) {
        ps += __shfl_xor_sync(0xffffffffu, ps, o);
        ns += __shfl_xor_sync(0xffffffffu, ns, o);
    }
    float h0 = __ldg(bp1 + lane), h1 = __ldg(bp1 + lane + 32);
    #pragma unroll 4
    for (int k = 0; k < 128; k++) {
        float srcv = (k < 32) ? u0 : (k < 64) ? u1 : (k < 96) ? p0 : p1;
        float v = __shfl_sync(0xffffffffu, srcv, k & 31);
        h0 += __ldg(Wp1 + lane * 128 + k) * v;
        h1 += __ldg(Wp1 + (lane + 32) * 128 + k) * v;
    }
    h0 = lrelu(h0); h1 = lrelu(h1);
    float pp = __ldg(Wp2 + lane) * h0 + __ldg(Wp2 + lane + 32) * h1;
    #pragma unroll
    for (int o = 16; o; o >>= 1) pp += __shfl_xor_sync(0xffffffffu, pp, o);
    if (lane == 0) {
        out_pos[w] = ps;
        out_neg[w] = ns;
        out_pred[w] = 1.f / (1.f + __expf(-(pp + __ldg(bp2))));
    }
}

// ---------------- launch ----------------
extern "C" void kernel_launch(void* const* d_in, const int* in_sizes, int n_in,
                              void* d_out, int out_size)
{
    const float* feat   = (const float*)d_in[0];
    const float* ufeat  = (const float*)d_in[1];
    const float* Wm     = (const float*)d_in[2];
    const float* bm     = (const float*)d_in[3];
    const float* Wu     = (const float*)d_in[4];
    const float* bu     = (const float*)d_in[5];
    const float* Wgat   = (const float*)d_in[6];
    const float* bgat   = (const float*)d_in[7];
    const float* Wl1    = (const float*)d_in[8];
    const float* bl1    = (const float*)d_in[9];
    const float* Wg1    = (const float*)d_in[10];
    const float* bg1    = (const float*)d_in[11];
    const float* id_emb = (const float*)d_in[12];
    const float* Wp1    = (const float*)d_in[13];
    const float* bp1    = (const float*)d_in[14];
    const float* Wp2    = (const float*)d_in[15];
    const float* bp2    = (const float*)d_in[16];
    const int*   ei     = (const int*)d_in[17];
    const int*   un     = (const int*)d_in[18];
    const int*   pit    = (const int*)d_in[19];
    const int*   nit    = (const int*)d_in[20];

    float* out      = (float*)d_out;
    float* out_pos  = out;
    float* out_neg  = out + NB;
    float* rep      = out + 2 * NB;
    float* out_pred = out + 2 * NB + (size_t)NN * DX;

    static cudaStream_t s_side = nullptr;
    static cudaEvent_t ev_fork = nullptr, ev_join = nullptr, ev_a0 = nullptr, ev_a1 = nullptr;
    if (!s_side) {
        cudaStreamCreateWithFlags(&s_side, cudaStreamNonBlocking);
        cudaEventCreateWithFlags(&ev_fork, cudaEventDisableTiming);
        cudaEventCreateWithFlags(&ev_join, cudaEventDisableTiming);
        cudaEventCreateWithFlags(&ev_a0,   cudaEventDisableTiming);
        cudaEventCreateWithFlags(&ev_a1,   cudaEventDisableTiming);
        cudaFuncSetAttribute(k_gemm_fused, cudaFuncAttributeMaxDynamicSharedMemorySize, 131072);
        cudaFuncSetAttribute(k_rep,        cudaFuncAttributeMaxDynamicSharedMemorySize, 196608);
    }

    // fork: CSR build chain on side stream, GEMM on main stream
    cudaEventRecord(ev_fork, 0);
    cudaStreamWaitEvent(s_side, ev_fork, 0);

    k_zero <<<(NN + 255) / 256, 256, 0, s_side>>>();
    k_hist <<<(NE + 255) / 256, 256, 0, s_side>>>(ei);
    k_scan1<<<SCANB, SCANT, 0, s_side>>>();
    k_scan2<<<1, 512, 0, s_side>>>();
    k_scan3<<<SCANB, SCANT, 0, s_side>>>();
    k_build<<<(NE + 255) / 256, 256, 0, s_side>>>(ei);

    k_gemm_fused<<<782, 512, 131072>>>(feat, ufeat, Wm, bm, Wu, bu, Wgat);

    cudaEventRecord(ev_join, s_side);
    cudaStreamWaitEvent(0, ev_join, 0);

    // pipeline: aggr half0 -> { rep half0 (main) || aggr half1 (side) } -> rep half1
    k_aggr<<<(NSPLIT * 32 + 511) / 512, 512>>>(bgat, 0, NSPLIT);
    cudaEventRecord(ev_a0, 0);
    cudaStreamWaitEvent(s_side, ev_a0, 0);
    k_aggr<<<((NN - NSPLIT) * 32 + 511) / 512, 512, 0, s_side>>>(bgat, NSPLIT, NN - NSPLIT);
    cudaEventRecord(ev_a1, s_side);

    k_rep<<<RBLK0, 512, 196608>>>(Wl1, bl1, Wg1, bg1, id_emb, rep, 0);
    cudaStreamWaitEvent(0, ev_a1, 0);
    k_rep<<<RBLK1, 512, 196608>>>(Wl1, bl1, Wg1, bg1, id_emb, rep, RBLK0);

    k_batch<<<NB / 8, 256>>>(rep, un, pit, nit, Wp1, bp1, Wp2, bp2,
                             out_pos, out_neg, out_pred);
}

// round 17
// speedup vs baseline: 1.0373x; 1.0186x over previous
#include <cuda_runtime.h>
#include <math.h>

#define NN     100000
#define NITEM  80000
#define DD     128
#define DX     64
#define NE     800000
#define NB     4096
#define NSPLIT 50048          // = 391 * 128 (proven split)
#define RBLK0  391
#define RBLK1  391
#define SCANT  256
#define SCANB  391            // = ceil(NN / 256)

// ---------------- device scratch ----------------
__device__ __align__(16) float g_x [(size_t)NN * DD];
__device__ __align__(16) float g_xw[(size_t)NN * DD];
__device__ __align__(16) float g_h [(size_t)NN * DD];
__device__ int g_deg[NN];
__device__ int g_cnt[NN];
__device__ int g_cur[NN];
__device__ int g_off[NN + 1];
__device__ int g_csr_src[NE];
__device__ int g_psum[SCANB];
__device__ int g_pbase[SCANB];

__device__ __forceinline__ float lrelu(float v) { return v > 0.f ? v : 0.01f * v; }

// ---------------- packed f32x2 helpers (Blackwell FFMA2) ----------------
__device__ __forceinline__ unsigned long long dup2(float a) {
    unsigned long long r;
    asm("mov.b64 %0, {%1, %1};" : "=l"(r) : "r"(__float_as_uint(a)));
    return r;
}
__device__ __forceinline__ void fma2(unsigned long long& d, unsigned long long a,
                                     unsigned long long b) {
    asm("fma.rn.f32x2 %0, %1, %2, %0;" : "+l"(d) : "l"(a), "l"(b));
}
__device__ __forceinline__ float lo32(unsigned long long v) {
    return __uint_as_float((unsigned)v);
}
__device__ __forceinline__ float hi32(unsigned long long v) {
    return __uint_as_float((unsigned)(v >> 32));
}

// 8x4 per-thread microtile GEMM over K=128. A stride 128, B stride LDB.
template <int LDB>
__device__ __forceinline__ void mmtile4(const float* __restrict__ As,
                                        const float* __restrict__ Bs,
                                        int r0, int c0, float (&out)[8][4]) {
    unsigned long long acc[8][2];
    #pragma unroll
    for (int r = 0; r < 8; r++) { acc[r][0] = 0ull; acc[r][1] = 0ull; }
    #pragma unroll 1
    for (int k = 0; k < 128; k += 4) {
        float4 av[8];
        #pragma unroll
        for (int r = 0; r < 8; r++)
            av[r] = *(const float4*)(As + (r0 + r) * 128 + k);
        #pragma unroll
        for (int kk = 0; kk < 4; kk++) {
            ulonglong2 b01 = *(const ulonglong2*)(Bs + (k + kk) * LDB + c0);
            #pragma unroll
            for (int r = 0; r < 8; r++) {
                float a = (kk == 0) ? av[r].x : (kk == 1) ? av[r].y
                        : (kk == 2) ? av[r].z : av[r].w;
                unsigned long long ad = dup2(a);
                fma2(acc[r][0], ad, b01.x);
                fma2(acc[r][1], ad, b01.y);
            }
        }
    }
    #pragma unroll
    for (int r = 0; r < 8; r++) {
        out[r][0] = lo32(acc[r][0]); out[r][1] = hi32(acc[r][0]);
        out[r][2] = lo32(acc[r][1]); out[r][3] = hi32(acc[r][1]);
    }
}

// ---------------- zero counters ----------------
__global__ void k_zero() {
    int i = blockIdx.x * 256 + threadIdx.x;
    if (i < NN) { g_deg[i] = 0; g_cnt[i] = 0; g_cur[i] = 0; }
}

// ---------------- histogram ----------------
__global__ void k_hist(const int* __restrict__ ei) {
    int e = blockIdx.x * 256 + threadIdx.x;
    if (e < NE) {
        atomicAdd(&g_deg[__ldg(ei + e)], 1);
        atomicAdd(&g_cnt[__ldg(ei + NE + e)], 1);
    }
}

// ---------------- parallel scan pass 1: per-block reduction (256 thr) -------------
__global__ void __launch_bounds__(SCANT) k_scan1() {
    __shared__ int sm[SCANT];
    const int t = threadIdx.x, b = blockIdx.x;
    int i = b * SCANT + t;
    sm[t] = (i < NN) ? g_cnt[i] : 0;
    __syncthreads();
    #pragma unroll
    for (int s = SCANT / 2; s > 0; s >>= 1) {
        if (t < s) sm[t] += sm[t + s];
        __syncthreads();
    }
    if (t == 0) g_psum[b] = sm[0];
}

// ---------------- parallel scan pass 2: scan the 391 block sums (1 block) ---------
__global__ void __launch_bounds__(512) k_scan2() {
    __shared__ int sm[512];
    const int t = threadIdx.x;
    int v = (t < SCANB) ? g_psum[t] : 0;
    sm[t] = v;
    __syncthreads();
    #pragma unroll
    for (int off = 1; off < 512; off <<= 1) {
        int u = (t >= off) ? sm[t - off] : 0;
        __syncthreads();
        sm[t] += u;
        __syncthreads();
    }
    if (t < SCANB) g_pbase[t] = sm[t] - v;
    if (t == SCANB - 1) g_off[NN] = sm[t];
}

// ---------------- parallel scan pass 3: block-local scan + base (256 thr) ---------
__global__ void __launch_bounds__(SCANT) k_scan3() {
    __shared__ int sm[SCANT];
    const int t = threadIdx.x, b = blockIdx.x;
    int i = b * SCANT + t;
    int v = (i < NN) ? g_cnt[i] : 0;
    sm[t] = v;
    __syncthreads();
    #pragma unroll
    for (int off = 1; off < SCANT; off <<= 1) {
        int u = (t >= off) ? sm[t - off] : 0;
        __syncthreads();
        sm[t] += u;
        __syncthreads();
    }
    if (i < NN) g_off[i] = g_pbase[b] + sm[t] - v;
}

// ---------------- CSR build ----------------
__global__ void k_build(const int* __restrict__ ei) {
    int e = blockIdx.x * 256 + threadIdx.x;
    if (e >= NE) return;
    int sj = __ldg(ei + e);
    int di = __ldg(ei + NE + e);
    int pos = g_off[di] + atomicAdd(&g_cur[di], 1);
    g_csr_src[pos] = sj;
}

// ---------------- fused GAT aggregation over node range ----------
__global__ void __launch_bounds__(256) k_aggr(const float* __restrict__ bgat,
                                              int base, int count) {
    int gt = blockIdx.x * 256 + threadIdx.x;
    int wi = gt >> 5, lane = gt & 31;
    if (wi >= count) return;
    int w = base + wi;

    float4 xd = *((const float4*)(g_xw + (size_t)w * DD) + lane);
    int p   = __ldg(&g_off[w]);
    int end = __ldg(&g_off[w + 1]);

    float4 acc = make_float4(0.f, 0.f, 0.f, 0.f);
    float s = 0.f;

    float4 a; float dg;
    if (p < end) {
        int sj = __ldg(&g_csr_src[p]);
        a  = *((const float4*)(g_xw + (size_t)sj * DD) + lane);
        dg = (float)__ldg(&g_deg[sj]);
    }
    while (p < end) {
        float4 a_n; float dg_n;
        if (p + 1 < end) {
            int sj = __ldg(&g_csr_src[p + 1]);
            a_n  = *((const float4*)(g_xw + (size_t)sj * DD) + lane);
            dg_n = (float)__ldg(&g_deg[sj]);
        }
        float d = a.x * xd.x + a.y * xd.y + a.z * xd.z + a.w * xd.w;
        #pragma unroll
        for (int o = 16; o; o >>= 1) d += __shfl_xor_sync(0xffffffffu, d, o);
        float gate = 1.f / (1.f + __expf(-rsqrtf(dg) * d));
        float ev = __expf(d * gate);
        s += ev;
        acc.x += ev * a.x; acc.y += ev * a.y;
        acc.z += ev * a.z; acc.w += ev * a.w;
        a = a_n; dg = dg_n; p++;
    }

    float inv_s = 1.f / (s + 1e-16f);
    float4 bb = __ldg((const float4*)bgat + lane);
    float4 h = make_float4(acc.x * inv_s + bb.x, acc.y * inv_s + bb.y,
                           acc.z * inv_s + bb.z, acc.w * inv_s + bb.w);
    float ss = h.x * h.x + h.y * h.y + h.z * h.z + h.w * h.w;
    #pragma unroll
    for (int o = 16; o; o >>= 1) ss += __shfl_xor_sync(0xffffffffu, ss, o);
    float inv = 1.f / fmaxf(sqrtf(ss), 1e-12f);
    h.x = lrelu(h.x * inv); h.y = lrelu(h.y * inv);
    h.z = lrelu(h.z * inv); h.w = lrelu(h.w * inv);
    *((float4*)(g_h + (size_t)w * DD) + lane) = h;
}

// ---------------- fused: x = l2norm(tanh(feat@W.T+b)); xw = x@W_gat ----------------
__global__ void __launch_bounds__(512, 1) k_gemm_fused(
    const float* __restrict__ feat, const float* __restrict__ ufeat,
    const float* __restrict__ Wm, const float* __restrict__ bm,
    const float* __restrict__ Wu, const float* __restrict__ bu,
    const float* __restrict__ Wg)
{
    extern __shared__ float smx[];
    float* As = smx;            // 128 x 128
    float* Bs = smx + 16384;    // 128 x 128
    const int row0 = blockIdx.x * 128;
    const bool user = row0 >= NITEM;
    const float* A    = user ? (ufeat + (size_t)(row0 - NITEM) * DD)
                             : (feat  + (size_t)row0 * DD);
    const float* W    = user ? Wu : Wm;
    const float* bias = user ? bu : bm;
    int rowlim = NN - row0; if (rowlim > 128) rowlim = 128;
    const int tid = threadIdx.x;

    for (int i = tid; i < 128 * 32; i += 512) {
        int r = i >> 5, c4 = i & 31;
        float4 v = make_float4(0.f, 0.f, 0.f, 0.f);
        if (r < rowlim) v = __ldg((const float4*)A + (size_t)r * 32 + c4);
        *(float4*)&As[r * 128 + c4 * 4] = v;
    }
    for (int i = tid; i < 128 * 32; i += 512) {
        int j = i & 127, c4 = i >> 7;
        float4 v = __ldg((const float4*)W + j * 32 + c4);
        Bs[(c4 * 4 + 0) * 128 + j] = v.x;
        Bs[(c4 * 4 + 1) * 128 + j] = v.y;
        Bs[(c4 * 4 + 2) * 128 + j] = v.z;
        Bs[(c4 * 4 + 3) * 128 + j] = v.w;
    }
    __syncthreads();

    const int r0 = (tid >> 5) * 8, c0 = (tid & 31) * 4;
    float v[8][4];
    mmtile4<128>(As, Bs, r0, c0, v);

    float4 bb = __ldg((const float4*)(bias + c0));
    float bcol[4] = {bb.x, bb.y, bb.z, bb.w};
    #pragma unroll
    for (int r = 0; r < 8; r++) {
        float ss = 0.f;
        #pragma unroll
        for (int c = 0; c < 4; c++) {
            float t = tanhf(v[r][c] + bcol[c]);
            v[r][c] = t; ss += t * t;
        }
        #pragma unroll
        for (int o = 16; o; o >>= 1) ss += __shfl_xor_sync(0xffffffffu, ss, o);
        float inv = 1.f / fmaxf(sqrtf(ss), 1e-12f);
        #pragma unroll
        for (int c = 0; c < 4; c++) v[r][c] *= inv;
        int grow = row0 + r0 + r;
        if (grow < NN)
            *(float4*)&g_x[(size_t)grow * 128 + c0] =
                make_float4(v[r][0], v[r][1], v[r][2], v[r][3]);
    }
    __syncthreads();

    #pragma unroll
    for (int r = 0; r < 8; r++)
        *(float4*)&As[(r0 + r) * 128 + c0] =
            make_float4(v[r][0], v[r][1], v[r][2], v[r][3]);
    for (int i = tid; i < 128 * 32; i += 512) {
        int kk = i >> 5, c4 = i & 31;
        float4 w = __ldg((const float4*)Wg + kk * 32 + c4);
        *(float4*)&Bs[kk * 128 + c4 * 4] = w;
    }
    __syncthreads();

    mmtile4<128>(As, Bs, r0, c0, v);
    #pragma unroll
    for (int r = 0; r < 8; r++) {
        int grow = row0 + r0 + r;
        if (grow < NN)
            *(float4*)&g_xw[(size_t)grow * 128 + c0] =
                make_float4(v[r][0], v[r][1], v[r][2], v[r][3]);
    }
}

// ---------------- rep = lrelu(h@Wg1.T+bg1 + lrelu(x@Wl1.T+bl1) + id_emb) ----------------
__global__ void __launch_bounds__(512, 1) k_rep(
    const float* __restrict__ Wl1, const float* __restrict__ bl1,
    const float* __restrict__ Wg1, const float* __restrict__ bg1,
    const float* __restrict__ id_emb, float* __restrict__ rep, int blk0)
{
    extern __shared__ float smx[];
    float* Xs  = smx;            // 128 x 128
    float* Hs  = smx + 16384;    // 128 x 128
    float* W1s = smx + 32768;    // 128 x 64, later epilogue buf
    float* Wgs = smx + 40960;    // 128 x 64
    const int row0 = (blockIdx.x + blk0) * 128;
    int rowlim = NN - row0; if (rowlim > 128) rowlim = 128;
    const int tid = threadIdx.x;

    for (int i = tid; i < 128 * 32; i += 512) {
        int r = i >> 5, c4 = i & 31;
        float4 vx = make_float4(0.f, 0.f, 0.f, 0.f), vh = vx;
        if (r < rowlim) {
            vx = *((const float4*)(g_x + (size_t)(row0 + r) * 128) + c4);
            vh = *((const float4*)(g_h + (size_t)(row0 + r) * 128) + c4);
        }
        *(float4*)&Xs[r * 128 + c4 * 4] = vx;
        *(float4*)&Hs[r * 128 + c4 * 4] = vh;
    }
    for (int i = tid; i < 64 * 32; i += 512) {
        int j = i & 63, c4 = i >> 6;
        float4 v1 = __ldg((const float4*)Wl1 + j * 32 + c4);
        float4 vg = __ldg((const float4*)Wg1 + j * 32 + c4);
        W1s[(c4 * 4 + 0) * 64 + j] = v1.x; W1s[(c4 * 4 + 1) * 64 + j] = v1.y;
        W1s[(c4 * 4 + 2) * 64 + j] = v1.z; W1s[(c4 * 4 + 3) * 64 + j] = v1.w;
        Wgs[(c4 * 4 + 0) * 64 + j] = vg.x; Wgs[(c4 * 4 + 1) * 64 + j] = vg.y;
        Wgs[(c4 * 4 + 2) * 64 + j] = vg.z; Wgs[(c4 * 4 + 3) * 64 + j] = vg.w;
    }
    __syncthreads();

    const int half = tid >> 8, t = tid & 255;
    const int r0 = (t >> 4) * 8, c0 = (t & 15) * 4;
    const float* Ablk = half ? Hs : Xs;
    const float* Wblk = half ? Wgs : W1s;
    float v[8][4];
    mmtile4<64>(Ablk, Wblk, r0, c0, v);
    __syncthreads();

    float* buf = W1s;
    if (half == 0) {
        float4 b0 = __ldg((const float4*)(bl1 + c0));
        float bc[4] = {b0.x, b0.y, b0.z, b0.w};
        #pragma unroll
        for (int r = 0; r < 8; r++) {
            int grow = row0 + r0 + r;
            float4 e0 = make_float4(0.f, 0.f, 0.f, 0.f);
            if (grow < NN)
                e0 = __ldg((const float4*)(id_emb + (size_t)grow * 64 + c0));
            float em[4] = {e0.x, e0.y, e0.z, e0.w};
            #pragma unroll
            for (int c = 0; c < 4; c++)
                buf[(r0 + r) * 64 + c0 + c] = lrelu(v[r][c] + bc[c]) + em[c];
        }
    }
    __syncthreads();
    if (half == 1) {
        float4 b0 = __ldg((const float4*)(bg1 + c0));
        float bc[4] = {b0.x, b0.y, b0.z, b0.w};
        #pragma unroll
        for (int r = 0; r < 8; r++) {
            int grow = row0 + r0 + r;
            if (grow < NN) {
                float o[4];
                #pragma unroll
                for (int c = 0; c < 4; c++)
                    o[c] = lrelu(v[r][c] + bc[c] + buf[(r0 + r) * 64 + c0 + c]);
                *(float4*)&rep[(size_t)grow * 64 + c0] =
                    make_float4(o[0], o[1], o[2], o[3]);
            }
        }
    }
}

// ---------------- batch head ----------------
__global__ void k_batch(const float* __restrict__ rep,
                        const int* __restrict__ un, const int* __restrict__ pit,
                        const int* __restrict__ nit,
                        const float* __restrict__ Wp1, const float* __restrict__ bp1,
                        const float* __restrict__ Wp2, const float* __restrict__ bp2,
                        float* __restrict__ out_pos, float* __restrict__ out_neg,
                        float* __restrict__ out_pred)
{
    int gt = blockIdx.x * 256 + threadIdx.x;
    int w = gt >> 5, lane = gt & 31;
    if (w >= NB) return;
    int iu = __ldg(un + w), ip = __ldg(pit + w), inn = __ldg(nit + w);
    float u0 = __ldg(rep + (size_t)iu * DX + lane), u1 = __ldg(rep + (size_t)iu * DX + 32 + lane);
    float p0 = __ldg(rep + (size_t)ip * DX + lane), p1 = __ldg(rep + (size_t)ip * DX + 32 + lane);
    float n0 = __ldg(rep + (size_t)inn * DX + lane), n1 = __ldg(rep + (size_t)inn * DX + 32 + lane);
    float ps = u0 * p0 + u1 * p1;
    float ns = u0 * n0 + u1 * n1;
    #pragma unroll
    for (int o = 16; o; o >>= 1) {
        ps += __shfl_xor_sync(0xffffffffu, ps, o);
        ns += __shfl_xor_sync(0xffffffffu, ns, o);
    }
    float h0 = __ldg(bp1 + lane), h1 = __ldg(bp1 + lane + 32);
    #pragma unroll 4
    for (int k = 0; k < 128; k++) {
        float srcv = (k < 32) ? u0 : (k < 64) ? u1 : (k < 96) ? p0 : p1;
        float v = __shfl_sync(0xffffffffu, srcv, k & 31);
        h0 += __ldg(Wp1 + lane * 128 + k) * v;
        h1 += __ldg(Wp1 + (lane + 32) * 128 + k) * v;
    }
    h0 = lrelu(h0); h1 = lrelu(h1);
    float pp = __ldg(Wp2 + lane) * h0 + __ldg(Wp2 + lane + 32) * h1;
    #pragma unroll
    for (int o = 16; o; o >>= 1) pp += __shfl_xor_sync(0xffffffffu, pp, o);
    if (lane == 0) {
        out_pos[w] = ps;
        out_neg[w] = ns;
        out_pred[w] = 1.f / (1.f + __expf(-(pp + __ldg(bp2))));
    }
}

// ---------------- launch ----------------
extern "C" void kernel_launch(void* const* d_in, const int* in_sizes, int n_in,
                              void* d_out, int out_size)
{
    const float* feat   = (const float*)d_in[0];
    const float* ufeat  = (const float*)d_in[1];
    const float* Wm     = (const float*)d_in[2];
    const float* bm     = (const float*)d_in[3];
    const float* Wu     = (const float*)d_in[4];
    const float* bu     = (const float*)d_in[5];
    const float* Wgat   = (const float*)d_in[6];
    const float* bgat   = (const float*)d_in[7];
    const float* Wl1    = (const float*)d_in[8];
    const float* bl1    = (const float*)d_in[9];
    const float* Wg1    = (const float*)d_in[10];
    const float* bg1    = (const float*)d_in[11];
    const float* id_emb = (const float*)d_in[12];
    const float* Wp1    = (const float*)d_in[13];
    const float* bp1    = (const float*)d_in[14];
    const float* Wp2    = (const float*)d_in[15];
    const float* bp2    = (const float*)d_in[16];
    const int*   ei     = (const int*)d_in[17];
    const int*   un     = (const int*)d_in[18];
    const int*   pit    = (const int*)d_in[19];
    const int*   nit    = (const int*)d_in[20];

    float* out      = (float*)d_out;
    float* out_pos  = out;
    float* out_neg  = out + NB;
    float* rep      = out + 2 * NB;
    float* out_pred = out + 2 * NB + (size_t)NN * DX;

    static cudaStream_t s_side = nullptr;
    static cudaEvent_t ev_fork = nullptr, ev_join = nullptr, ev_a0 = nullptr, ev_a1 = nullptr;
    if (!s_side) {
        cudaStreamCreateWithFlags(&s_side, cudaStreamNonBlocking);
        cudaEventCreateWithFlags(&ev_fork, cudaEventDisableTiming);
        cudaEventCreateWithFlags(&ev_join, cudaEventDisableTiming);
        cudaEventCreateWithFlags(&ev_a0,   cudaEventDisableTiming);
        cudaEventCreateWithFlags(&ev_a1,   cudaEventDisableTiming);
        cudaFuncSetAttribute(k_gemm_fused, cudaFuncAttributeMaxDynamicSharedMemorySize, 131072);
        cudaFuncSetAttribute(k_rep,        cudaFuncAttributeMaxDynamicSharedMemorySize, 196608);
    }

    // fork: CSR build chain on side stream, GEMM on main stream
    cudaEventRecord(ev_fork, 0);
    cudaStreamWaitEvent(s_side, ev_fork, 0);

    k_zero <<<(NN + 255) / 256, 256, 0, s_side>>>();
    k_hist <<<(NE + 255) / 256, 256, 0, s_side>>>(ei);
    k_scan1<<<SCANB, SCANT, 0, s_side>>>();
    k_scan2<<<1, 512, 0, s_side>>>();
    k_scan3<<<SCANB, SCANT, 0, s_side>>>();
    k_build<<<(NE + 255) / 256, 256, 0, s_side>>>(ei);

    k_gemm_fused<<<782, 512, 131072>>>(feat, ufeat, Wm, bm, Wu, bu, Wgat);

    cudaEventRecord(ev_join, s_side);
    cudaStreamWaitEvent(0, ev_join, 0);

    // pipeline: aggr half0 -> { rep half0 (main) || aggr half1 (side) } -> rep half1
    k_aggr<<<(NSPLIT * 32 + 255) / 256, 256>>>(bgat, 0, NSPLIT);
    cudaEventRecord(ev_a0, 0);
    cudaStreamWaitEvent(s_side, ev_a0, 0);
    k_aggr<<<((NN - NSPLIT) * 32 + 255) / 256, 256, 0, s_side>>>(bgat, NSPLIT, NN - NSPLIT);
    cudaEventRecord(ev_a1, s_side);

    k_rep<<<RBLK0, 512, 196608>>>(Wl1, bl1, Wg1, bg1, id_emb, rep, 0);
    cudaStreamWaitEvent(0, ev_a1, 0);
    k_rep<<<RBLK1, 512, 196608>>>(Wl1, bl1, Wg1, bg1, id_emb, rep, RBLK0);

    k_batch<<<NB / 8, 256>>>(rep, un, pit, nit, Wp1, bp1, Wp2, bp2,
                             out_pos, out_neg, out_pred);
}